// round 11
// baseline (speedup 1.0000x reference)
#include <cuda_runtime.h>
#include <cuda_bf16.h>
#include <math.h>
#include <stdint.h>

#define Bq 256
#define Sq 10
#define Hq 1024
#define Vq 32000
#define Tq 10
#define BT (Bq * Tq)

// ---------------- device scratch (no allocation) ----------------
__device__ __align__(16) float g_keysA[(size_t)Bq * Sq * 4096];  // [ keysW(1024) | keysC(3072) ]
__device__ int   g_tokens[Bq * Tq];
__device__ __align__(16) float g_qgh[Bq * 4096];
__device__ __align__(16) float g_gie[(size_t)BT * 3 * Hq];
__device__ __align__(16) float g_h0[Bq * Hq];
__device__ __align__(16) float g_h1[Bq * Hq];
__device__ __align__(16) float g_logits_all[(size_t)BT * Vq];
__device__ __align__(16) float g_bcat[4096];
__device__ __align__(16) float g_bkA[4096];

__device__ __align__(16) __nv_bfloat16 g_enc2[(size_t)Bq * Sq * 3 * Hq];
__device__ __align__(16) __nv_bfloat16 g_e2[(size_t)BT * 3 * Hq];
__device__ __align__(16) __nv_bfloat16 g_WkA2[(size_t)4096 * 3 * Hq];   // [Wa; Wc] packed
__device__ __align__(16) __nv_bfloat16 g_Wqh2[(size_t)4096 * 3 * Hq];   // [Ua; Whh] packed
__device__ __align__(16) __nv_bfloat16 g_We2[(size_t)3 * Hq * 3 * Hq];
__device__ __align__(16) __nv_bfloat16 g_h2[Bq * 3 * Hq];
__device__ __align__(16) __nv_bfloat16 g_hall[(size_t)BT * Hq];
__device__ __align__(16) __nv_bfloat16 g_Wout_bf[(size_t)Vq * Hq];

// ---------------- bf16 HMMA GEMM: 3-stage cp.async ring, one barrier per K-iter ----------------
template <int BM, int BN, int BK, int WM, int WN, int MINB>
__global__ void __launch_bounds__((BM / WM) * (BN / WN) * 32, MINB)
gemm_bf16_bias(const __nv_bfloat16* __restrict__ A, const __nv_bfloat16* __restrict__ B,
               const float* __restrict__ bias, float* __restrict__ C,
               int M, int N, int K)
{
    constexpr int WARPS_M = BM / WM;
    constexpr int WARPS_N = BN / WN;
    constexpr int THREADS = WARPS_M * WARPS_N * 32;
    constexpr int PAD = 8;
    constexpr int LDS_ = BK + PAD;
    constexpr int MI = WM / 16;
    constexpr int NI = WN / 8;

    extern __shared__ char smem_raw[];
    __nv_bfloat16* As = (__nv_bfloat16*)smem_raw;                         // [3][BM*LDS_]
    __nv_bfloat16* Bs = (__nv_bfloat16*)(smem_raw + 3 * BM * LDS_ * 2);   // [3][BN*LDS_]

    const int tid = threadIdx.x;
    const int wid = tid / 32, lane = tid % 32;
    const int wm = (wid / WARPS_N) * WM;
    const int wn = (wid % WARPS_N) * WN;
    const int bm = blockIdx.y * BM;
    const int bn = blockIdx.x * BN;

    constexpr int A_CH = BM * BK / 8;
    constexpr int B_CH = BN * BK / 8;
    constexpr int CPR = BK / 8;

    const int NK = K / BK;

    auto load_stage = [&](int stage) {
        __nv_bfloat16* Asd = As + (stage % 3) * BM * LDS_;
        __nv_bfloat16* Bsd = Bs + (stage % 3) * BN * LDS_;
        const int k0 = stage * BK;
#pragma unroll
        for (int c = tid; c < A_CH; c += THREADS) {
            int r = c / CPR, cc = (c % CPR) * 8;
            uint32_t sdst = (uint32_t)__cvta_generic_to_shared(&Asd[r * LDS_ + cc]);
            const __nv_bfloat16* src = &A[(size_t)(bm + r) * K + k0 + cc];
            asm volatile("cp.async.cg.shared.global [%0], [%1], 16;" :: "r"(sdst), "l"(src));
        }
#pragma unroll
        for (int c = tid; c < B_CH; c += THREADS) {
            int r = c / CPR, cc = (c % CPR) * 8;
            uint32_t sdst = (uint32_t)__cvta_generic_to_shared(&Bsd[r * LDS_ + cc]);
            const __nv_bfloat16* src = &B[(size_t)(bn + r) * K + k0 + cc];
            asm volatile("cp.async.cg.shared.global [%0], [%1], 16;" :: "r"(sdst), "l"(src));
        }
        asm volatile("cp.async.commit_group;");
    };

    float acc[MI][NI][4];
#pragma unroll
    for (int i = 0; i < MI; i++)
#pragma unroll
        for (int j = 0; j < NI; j++)
#pragma unroll
            for (int k = 0; k < 4; k++) acc[i][j][k] = 0.f;

    // prologue: stages 0 and 1 in flight
    load_stage(0);
    if (NK > 1) load_stage(1);

    const int a_row = lane % 16;
    const int a_col = (lane / 16) * 8;
    const int b_t   = lane & 15;
    const int b_row = b_t % 8;
    const int b_col = (b_t / 8) * 8;

    for (int kt = 0; kt < NK; kt++) {
        // drain so stage kt is resident
        if (kt + 1 < NK) {
            asm volatile("cp.async.wait_group 1;");
        } else {
            asm volatile("cp.async.wait_group 0;");
        }
        __syncthreads();  // stage kt visible AND all warps done computing kt-1

        // prefetch kt+2 into buffer (kt+2)%3 == (kt-1)%3 (safe after barrier)
        if (kt + 2 < NK) load_stage(kt + 2);

        __nv_bfloat16* Asb = As + (kt % 3) * BM * LDS_;
        __nv_bfloat16* Bsb = Bs + (kt % 3) * BN * LDS_;

#pragma unroll
        for (int kk = 0; kk < BK; kk += 16) {
            uint32_t af[MI][4];
#pragma unroll
            for (int mi = 0; mi < MI; mi++) {
                uint32_t addr = (uint32_t)__cvta_generic_to_shared(
                    &Asb[(wm + mi * 16 + a_row) * LDS_ + kk + a_col]);
                asm volatile("ldmatrix.sync.aligned.m8n8.x4.shared.b16 {%0,%1,%2,%3}, [%4];"
                             : "=r"(af[mi][0]), "=r"(af[mi][1]), "=r"(af[mi][2]), "=r"(af[mi][3])
                             : "r"(addr));
            }
            uint32_t bf[NI][2];
#pragma unroll
            for (int ni = 0; ni < NI; ni++) {
                uint32_t addr = (uint32_t)__cvta_generic_to_shared(
                    &Bsb[(wn + ni * 8 + b_row) * LDS_ + kk + b_col]);
                asm volatile("ldmatrix.sync.aligned.m8n8.x2.shared.b16 {%0,%1}, [%2];"
                             : "=r"(bf[ni][0]), "=r"(bf[ni][1])
                             : "r"(addr));
            }
#pragma unroll
            for (int mi = 0; mi < MI; mi++) {
#pragma unroll
                for (int ni = 0; ni < NI; ni++) {
                    asm volatile(
                        "mma.sync.aligned.m16n8k16.row.col.f32.bf16.bf16.f32 "
                        "{%0,%1,%2,%3}, {%4,%5,%6,%7}, {%8,%9}, {%0,%1,%2,%3};"
                        : "+f"(acc[mi][ni][0]), "+f"(acc[mi][ni][1]),
                          "+f"(acc[mi][ni][2]), "+f"(acc[mi][ni][3])
                        : "r"(af[mi][0]), "r"(af[mi][1]), "r"(af[mi][2]), "r"(af[mi][3]),
                          "r"(bf[ni][0]), "r"(bf[ni][1]));
                }
            }
        }
    }

#pragma unroll
    for (int mi = 0; mi < MI; mi++) {
        int row0 = bm + wm + mi * 16 + lane / 4;
#pragma unroll
        for (int ni = 0; ni < NI; ni++) {
            int col = bn + wn + ni * 8 + 2 * (lane % 4);
            float2 bv = *(const float2*)&bias[col];
            float2 v0 = make_float2(acc[mi][ni][0] + bv.x, acc[mi][ni][1] + bv.y);
            float2 v1 = make_float2(acc[mi][ni][2] + bv.x, acc[mi][ni][3] + bv.y);
            *(float2*)&C[(size_t)row0 * N + col] = v0;
            *(float2*)&C[(size_t)(row0 + 8) * N + col] = v1;
        }
    }
}

// smem sizes (3 stages)
#define DSM_WIDE  (3 * (128 + 256) * (64 + 8) * 2)   // 165888  (128x256 tile, 1 CTA/SM)
#define DSM_SMALL (3 * (64 + 64) * (64 + 8) * 2)     // 55296   (64x64 tile, 4 CTA/SM)

// wide GEMM: BM=128, BN=256, WM=64, WN=64, 256 threads, min-blocks 1 (no reg cap)
#define GEMM_WIDE gemm_bf16_bias<128, 256, 64, 64, 64, 1>
// small GEMM for the recurrence loop
#define GEMM_SMALL gemm_bf16_bias<64, 64, 64, 32, 32, 4>

// ---------------- setup / pack kernels ----------------
__global__ void init_tokens_kernel(const int* __restrict__ target)
{
    int b = threadIdx.x;
    g_tokens[b * Tq + 0] = 0;  // SOS
    for (int t = 1; t < Tq; t++) g_tokens[b * Tq + t] = target[b * Tq + t - 1];
}

__global__ void f2bf_kernel(const float* __restrict__ src, __nv_bfloat16* __restrict__ dst, int n4)
{
    int i = blockIdx.x * blockDim.x + threadIdx.x;
    if (i >= n4) return;
    float4 v = ((const float4*)src)[i];
    __nv_bfloat162 lo = __floats2bfloat162_rn(v.x, v.y);
    __nv_bfloat162 hi = __floats2bfloat162_rn(v.z, v.w);
    uint2 o;
    o.x = *(uint32_t*)&lo;
    o.y = *(uint32_t*)&hi;
    ((uint2*)dst)[i] = o;
}

// Weight pack [hi|hi|lo]; src elem = src[n*stride + off + k]
__global__ void pack3_w_kernel(const float* __restrict__ src, __nv_bfloat16* __restrict__ dst,
                               int N, int K, int stride, int off)
{
    int i = blockIdx.x * blockDim.x + threadIdx.x;
    if (i >= N * K) return;
    int n = i / K, k = i % K;
    float w = src[(size_t)n * stride + off + k];
    __nv_bfloat16 hi = __float2bfloat16(w);
    __nv_bfloat16 lo = __float2bfloat16(w - __bfloat162float(hi));
    __nv_bfloat16* row = dst + (size_t)n * 3 * K;
    row[k] = hi; row[K + k] = hi; row[2 * K + k] = lo;
}

// Activation pack [hi|lo|hi]
__global__ void pack3_a_kernel(const float* __restrict__ src, __nv_bfloat16* __restrict__ dst,
                               int N, int K)
{
    int i = blockIdx.x * blockDim.x + threadIdx.x;
    if (i >= N * K) return;
    int n = i / K, k = i % K;
    float a = src[(size_t)n * K + k];
    __nv_bfloat16 hi = __float2bfloat16(a);
    __nv_bfloat16 lo = __float2bfloat16(a - __bfloat162float(hi));
    __nv_bfloat16* row = dst + (size_t)n * 3 * K;
    row[k] = hi; row[K + k] = lo; row[2 * K + k] = hi;
}

// embedding rows for ALL steps, packed [hi|lo|hi]; row r = t*Bq + b
__global__ void emb_pack_kernel(const float* __restrict__ emb)
{
    int i = blockIdx.x * blockDim.x + threadIdx.x;
    int r = i / Hq, j = i % Hq;
    int t = r / Bq, b = r % Bq;
    float v = emb[(size_t)g_tokens[b * Tq + t] * Hq + j];
    __nv_bfloat16 hi = __float2bfloat16(v);
    __nv_bfloat16 lo = __float2bfloat16(v - __bfloat162float(hi));
    __nv_bfloat16* row = g_e2 + (size_t)r * 3 * Hq;
    row[j] = hi; row[Hq + j] = lo; row[2 * Hq + j] = hi;
}

__global__ void bias_cat_kernel(const float* __restrict__ bua, const float* __restrict__ bhh,
                                const float* __restrict__ ba)
{
    int i = blockIdx.x * blockDim.x + threadIdx.x;  // 4096
    g_bcat[i] = (i < Hq) ? bua[i] : bhh[i - Hq];
    g_bkA[i]  = (i < Hq) ? ba[i] : 0.f;
}

__global__ void copy_h0_kernel(float* __restrict__ dst, const float* __restrict__ src)
{
    int i = blockIdx.x * blockDim.x + threadIdx.x;
    int b = i / Hq, j = i % Hq;
    float v = src[i];
    dst[i] = v;
    __nv_bfloat16 hi = __float2bfloat16(v);
    __nv_bfloat16 lo = __float2bfloat16(v - __bfloat162float(hi));
    __nv_bfloat16* row = g_h2 + (size_t)b * 3 * Hq;
    row[j] = hi; row[Hq + j] = lo; row[2 * Hq + j] = hi;
}

__global__ void copy_kernel(float* __restrict__ dst, const float* __restrict__ src)
{
    int i = blockIdx.x * blockDim.x + threadIdx.x;
    dst[i] = src[i];
}

// ---------------- fused attention + GRU (keysW/keysC from merged g_keysA) ----------------
__global__ void __launch_bounds__(128)
attn_gru_kernel(const float* __restrict__ Va, const float* __restrict__ bva,
                float* __restrict__ att_out,
                const float* __restrict__ hcur, float* __restrict__ hnext, int t)
{
    const int b = blockIdx.x;
    const int tid = threadIdx.x;

    float partial[Sq];
#pragma unroll
    for (int s = 0; s < Sq; s++) partial[s] = 0.f;

    for (int h = tid; h < Hq; h += 128) {
        float qv = g_qgh[b * 4096 + h];
        float va = Va[h];
#pragma unroll
        for (int s = 0; s < Sq; s++) {
            float kw = g_keysA[((size_t)b * Sq + s) * 4096 + h];
            partial[s] += va * tanhf(kw + qv);
        }
    }

    __shared__ float red[4][Sq];
    __shared__ float w[Sq];
    __shared__ float gic_s[3 * Hq];
    int lane = tid & 31, warp = tid >> 5;
#pragma unroll
    for (int s = 0; s < Sq; s++) {
        float v = partial[s];
#pragma unroll
        for (int o = 16; o > 0; o >>= 1) v += __shfl_xor_sync(0xffffffffu, v, o);
        if (lane == 0) red[warp][s] = v;
    }
    __syncthreads();

    if (tid == 0) {
        float scv[Sq], mx = -1e30f;
#pragma unroll
        for (int s = 0; s < Sq; s++) {
            scv[s] = red[0][s] + red[1][s] + red[2][s] + red[3][s] + bva[0];
            mx = fmaxf(mx, scv[s]);
        }
        float sum = 0.f;
#pragma unroll
        for (int s = 0; s < Sq; s++) { scv[s] = expf(scv[s] - mx); sum += scv[s]; }
        float inv = 1.f / sum;
#pragma unroll
        for (int s = 0; s < Sq; s++) w[s] = scv[s] * inv;
    }
    __syncthreads();

    if (tid < Sq) att_out[(size_t)b * (Tq * Sq) + t * Sq + tid] = w[tid];

    // gic = sum_s w[s] * keysC[b,s,:]  (keysC = cols 1024.. of g_keysA)
    const float* kA = g_keysA + (size_t)b * Sq * 4096 + 1024;
    for (int j = tid; j < 3 * Hq; j += 128) {
        float acc = 0.f;
#pragma unroll
        for (int s = 0; s < Sq; s++)
            acc += w[s] * kA[(size_t)s * 4096 + j];
        gic_s[j] = acc;
    }
    __syncthreads();

    // GRU pointwise for row b
    const float* gie = g_gie + (size_t)(t * Bq + b) * 3 * Hq;
    const float* gh  = g_qgh + (size_t)b * 4096 + Hq;
    __nv_bfloat16* h2row = g_h2 + (size_t)b * 3 * Hq;
    for (int j = tid; j < Hq; j += 128) {
        float r = 1.f / (1.f + expf(-(gie[j] + gic_s[j] + gh[j])));
        float z = 1.f / (1.f + expf(-(gie[Hq + j] + gic_s[Hq + j] + gh[Hq + j])));
        float n = tanhf(gie[2 * Hq + j] + gic_s[2 * Hq + j] + r * gh[2 * Hq + j]);
        float hv = (1.f - z) * n + z * hcur[b * Hq + j];
        hnext[b * Hq + j] = hv;
        g_hall[(size_t)(t * Bq + b) * Hq + j] = __float2bfloat16(hv);
        __nv_bfloat16 hi = __float2bfloat16(hv);
        __nv_bfloat16 lo = __float2bfloat16(hv - __bfloat162float(hi));
        h2row[j] = hi; h2row[Hq + j] = lo; h2row[2 * Hq + j] = hi;
    }
}

// ---------------- batched log_softmax (row r = t*Bq + b -> out[b][t]) ----------------
__global__ void __launch_bounds__(256)
logsoftmax_all_kernel(float* __restrict__ out)
{
    const int r = blockIdx.x, tid = threadIdx.x;
    const int t = r / Bq, b = r % Bq;
    const float* row = g_logits_all + (size_t)r * Vq;

    float m = -1e30f, s = 0.f;
    for (int v = tid; v < Vq; v += 256) {
        float x = row[v];
        float nm = fmaxf(m, x);
        s = s * expf(m - nm) + expf(x - nm);
        m = nm;
    }
    int lane = tid & 31, warp = tid >> 5;
#pragma unroll
    for (int o = 16; o > 0; o >>= 1) {
        float m2 = __shfl_xor_sync(0xffffffffu, m, o);
        float s2 = __shfl_xor_sync(0xffffffffu, s, o);
        float nm = fmaxf(m, m2);
        s = s * expf(m - nm) + s2 * expf(m2 - nm);
        m = nm;
    }
    __shared__ float sm[8], ss[8];
    __shared__ float lse_sh;
    if (lane == 0) { sm[warp] = m; ss[warp] = s; }
    __syncthreads();
    if (tid == 0) {
        float M = sm[0], S = ss[0];
#pragma unroll
        for (int i = 1; i < 8; i++) {
            float nm = fmaxf(M, sm[i]);
            S = S * expf(M - nm) + ss[i] * expf(sm[i] - nm);
            M = nm;
        }
        lse_sh = M + logf(S);
    }
    __syncthreads();
    float lse = lse_sh;
    float* orow = out + ((size_t)b * Tq + t) * Vq;
    for (int v = tid; v < Vq; v += 256) orow[v] = row[v] - lse;
}

// ---------------- launch ----------------
extern "C" void kernel_launch(void* const* d_in, const int* in_sizes, int n_in,
                              void* d_out, int out_size)
{
    const float* enc_out = (const float*)d_in[0];
    const float* enc_hid = (const float*)d_in[1];
    const int*   target  = (const int*)  d_in[2];
    const float* emb     = (const float*)d_in[3];
    const float* Wa      = (const float*)d_in[4];
    const float* ba      = (const float*)d_in[5];
    const float* Ua      = (const float*)d_in[6];
    const float* bua     = (const float*)d_in[7];
    const float* Va      = (const float*)d_in[8];
    const float* bva     = (const float*)d_in[9];
    const float* W_ih    = (const float*)d_in[10];
    const float* W_hh    = (const float*)d_in[11];
    const float* b_ih    = (const float*)d_in[12];
    const float* b_hh    = (const float*)d_in[13];
    const float* W_out   = (const float*)d_in[14];
    const float* b_out   = (const float*)d_in[15];

    float* out = (float*)d_out;
    const size_t HID_OFF = (size_t)Bq * Tq * Vq;
    const size_t ATT_OFF = HID_OFF + (size_t)Bq * Hq;

    float *keysA, *gie, *h0, *h1, *logitsA, *bcat, *bkA, *qgh;
    __nv_bfloat16 *enc2, *e2, *WkA2, *Wqh2, *We2, *h2, *hall, *WoutB;
    cudaGetSymbolAddress((void**)&keysA, g_keysA);
    cudaGetSymbolAddress((void**)&gie, g_gie);
    cudaGetSymbolAddress((void**)&h0, g_h0);
    cudaGetSymbolAddress((void**)&h1, g_h1);
    cudaGetSymbolAddress((void**)&logitsA, g_logits_all);
    cudaGetSymbolAddress((void**)&bcat, g_bcat);
    cudaGetSymbolAddress((void**)&bkA, g_bkA);
    cudaGetSymbolAddress((void**)&qgh, g_qgh);
    cudaGetSymbolAddress((void**)&enc2, g_enc2);
    cudaGetSymbolAddress((void**)&e2, g_e2);
    cudaGetSymbolAddress((void**)&WkA2, g_WkA2);
    cudaGetSymbolAddress((void**)&Wqh2, g_Wqh2);
    cudaGetSymbolAddress((void**)&We2, g_We2);
    cudaGetSymbolAddress((void**)&h2, g_h2);
    cudaGetSymbolAddress((void**)&hall, g_hall);
    cudaGetSymbolAddress((void**)&WoutB, g_Wout_bf);

    // raise dynamic smem limits (idempotent)
    cudaFuncSetAttribute((const void*)GEMM_WIDE,
                         cudaFuncAttributeMaxDynamicSharedMemorySize, DSM_WIDE);
    cudaFuncSetAttribute((const void*)GEMM_SMALL,
                         cudaFuncAttributeMaxDynamicSharedMemorySize, DSM_SMALL);

    // ---- setup (gie GEMM at launch #4 for ncu capture comparison) ----
    init_tokens_kernel<<<1, 256>>>(target);                                               // 1
    emb_pack_kernel<<<(BT * Hq) / 256, 256>>>(emb);                                       // 2
    pack3_w_kernel<<<(3 * Hq * Hq + 255) / 256, 256>>>(W_ih, We2, 3 * Hq, Hq, 2 * Hq, 0); // 3
    // gi_e all steps = E @ W_e^T + b_ih  (M=2560, N=3072, K=3072)                        // 4
    GEMM_WIDE<<<dim3(3 * Hq / 256, BT / 128), 256, DSM_WIDE>>>(
        e2, We2, b_ih, gie, BT, 3 * Hq, 3 * Hq);

    pack3_a_kernel<<<(Bq * Sq * Hq + 255) / 256, 256>>>(enc_out, enc2, Bq * Sq, Hq);
    pack3_w_kernel<<<(Hq * Hq + 255) / 256, 256>>>(Wa, WkA2, Hq, Hq, Hq, 0);
    pack3_w_kernel<<<(3 * Hq * Hq + 255) / 256, 256>>>(W_ih, WkA2 + (size_t)Hq * 3 * Hq,
                                                       3 * Hq, Hq, 2 * Hq, Hq);
    bias_cat_kernel<<<16, 256>>>(bua, b_hh, ba);
    // keysA = enc @ [Wa;Wc]^T + [ba|0]  (M=2560, N=4096, K=3072)
    GEMM_WIDE<<<dim3(4096 / 256, (Bq * Sq) / 128), 256, DSM_WIDE>>>(
        enc2, WkA2, bkA, keysA, Bq * Sq, 4096, 3 * Hq);

    copy_h0_kernel<<<(Bq * Hq) / 256, 256>>>(h0, enc_hid);
    f2bf_kernel<<<(Vq * Hq / 4 + 255) / 256, 256>>>(W_out, WoutB, Vq * Hq / 4);
    pack3_w_kernel<<<(Hq * Hq + 255) / 256, 256>>>(Ua, Wqh2, Hq, Hq, Hq, 0);
    pack3_w_kernel<<<(3 * Hq * Hq + 255) / 256, 256>>>(W_hh, Wqh2 + (size_t)Hq * 3 * Hq,
                                                       3 * Hq, Hq, Hq, 0);

    float* hcur = h0;
    float* hnext = h1;
    for (int t = 0; t < Tq; t++) {
        // [q | gh] = h @ [Ua; W_hh]^T + [bua | b_hh]  (M=256, N=4096, K=3072)
        GEMM_SMALL<<<dim3(4096 / 64, Bq / 64), 128, DSM_SMALL>>>(
            h2, Wqh2, bcat, qgh, Bq, 4096, 3 * Hq);
        attn_gru_kernel<<<Bq, 128>>>(Va, bva, out + ATT_OFF, hcur, hnext, t);
        float* tmp = hcur; hcur = hnext; hnext = tmp;
    }

    // logits for all steps = h_all @ W_out^T + b_out  (M=2560, N=32000, K=1024)
    GEMM_WIDE<<<dim3(Vq / 256, BT / 128), 256, DSM_WIDE>>>(
        hall, WoutB, b_out, logitsA, BT, Vq, Hq);
    logsoftmax_all_kernel<<<BT, 256>>>(out);

    copy_kernel<<<(Bq * Hq) / 256, 256>>>(out + HID_OFF, hcur);
}

// round 12
// speedup vs baseline: 1.4794x; 1.4794x over previous
#include <cuda_runtime.h>
#include <cuda_fp16.h>
#include <math.h>
#include <stdint.h>

#define Bq 256
#define Sq 10
#define Hq 1024
#define Vq 32000
#define Tq 10
#define BT (Bq * Tq)

// ---------------- device scratch (no allocation) ----------------
__device__ __align__(16) float g_keysA[(size_t)Bq * Sq * 4096];  // [ keysW(1024) | keysC(3072) ]
__device__ int   g_tokens[Bq * Tq];
__device__ __align__(16) float g_qgh[Bq * 4096];
__device__ __align__(16) float g_gie[(size_t)BT * 3 * Hq];
__device__ __align__(16) float g_h0[Bq * Hq];
__device__ __align__(16) float g_h1[Bq * Hq];
__device__ __align__(16) float g_logits_all[(size_t)BT * Vq];
__device__ __align__(16) float g_bcat[4096];
__device__ __align__(16) float g_bkA[4096];

__device__ __align__(16) __half g_enc_h[(size_t)Bq * Sq * Hq];
__device__ __align__(16) __half g_e_h[(size_t)BT * Hq];
__device__ __align__(16) __half g_WkA[(size_t)4096 * Hq];   // [Wa; Wc]
__device__ __align__(16) __half g_Wqh[(size_t)4096 * Hq];   // [Ua; Whh]
__device__ __align__(16) __half g_We[(size_t)3 * Hq * Hq];
__device__ __align__(16) __half g_h_h[Bq * Hq];
__device__ __align__(16) __half g_hall[(size_t)BT * Hq];
__device__ __align__(16) __half g_Wout_h[(size_t)Vq * Hq];

// ---------------- fp16 HMMA GEMM: 3-stage cp.async ring, one barrier per K-iter ----------------
template <int BM, int BN, int BK, int WM, int WN, int MINB>
__global__ void __launch_bounds__((BM / WM) * (BN / WN) * 32, MINB)
gemm_fp16_bias(const __half* __restrict__ A, const __half* __restrict__ B,
               const float* __restrict__ bias, float* __restrict__ C,
               int M, int N, int K)
{
    constexpr int WARPS_M = BM / WM;
    constexpr int WARPS_N = BN / WN;
    constexpr int THREADS = WARPS_M * WARPS_N * 32;
    constexpr int PAD = 8;
    constexpr int LDS_ = BK + PAD;
    constexpr int MI = WM / 16;
    constexpr int NI = WN / 8;

    extern __shared__ char smem_raw[];
    __half* As = (__half*)smem_raw;                          // [3][BM*LDS_]
    __half* Bs = (__half*)(smem_raw + 3 * BM * LDS_ * 2);    // [3][BN*LDS_]

    const int tid = threadIdx.x;
    const int wid = tid / 32, lane = tid % 32;
    const int wm = (wid / WARPS_N) * WM;
    const int wn = (wid % WARPS_N) * WN;
    const int bm = blockIdx.y * BM;
    const int bn = blockIdx.x * BN;

    constexpr int A_CH = BM * BK / 8;
    constexpr int B_CH = BN * BK / 8;
    constexpr int CPR = BK / 8;

    const int NK = K / BK;

    auto load_stage = [&](int stage) {
        __half* Asd = As + (stage % 3) * BM * LDS_;
        __half* Bsd = Bs + (stage % 3) * BN * LDS_;
        const int k0 = stage * BK;
#pragma unroll
        for (int c = tid; c < A_CH; c += THREADS) {
            int r = c / CPR, cc = (c % CPR) * 8;
            uint32_t sdst = (uint32_t)__cvta_generic_to_shared(&Asd[r * LDS_ + cc]);
            const __half* src = &A[(size_t)(bm + r) * K + k0 + cc];
            asm volatile("cp.async.cg.shared.global [%0], [%1], 16;" :: "r"(sdst), "l"(src));
        }
#pragma unroll
        for (int c = tid; c < B_CH; c += THREADS) {
            int r = c / CPR, cc = (c % CPR) * 8;
            uint32_t sdst = (uint32_t)__cvta_generic_to_shared(&Bsd[r * LDS_ + cc]);
            const __half* src = &B[(size_t)(bn + r) * K + k0 + cc];
            asm volatile("cp.async.cg.shared.global [%0], [%1], 16;" :: "r"(sdst), "l"(src));
        }
        asm volatile("cp.async.commit_group;");
    };

    float acc[MI][NI][4];
#pragma unroll
    for (int i = 0; i < MI; i++)
#pragma unroll
        for (int j = 0; j < NI; j++)
#pragma unroll
            for (int k = 0; k < 4; k++) acc[i][j][k] = 0.f;

    load_stage(0);
    if (NK > 1) load_stage(1);

    const int a_row = lane % 16;
    const int a_col = (lane / 16) * 8;
    const int b_t   = lane & 15;
    const int b_row = b_t % 8;
    const int b_col = (b_t / 8) * 8;

    for (int kt = 0; kt < NK; kt++) {
        if (kt + 1 < NK) {
            asm volatile("cp.async.wait_group 1;");
        } else {
            asm volatile("cp.async.wait_group 0;");
        }
        __syncthreads();

        if (kt + 2 < NK) load_stage(kt + 2);

        __half* Asb = As + (kt % 3) * BM * LDS_;
        __half* Bsb = Bs + (kt % 3) * BN * LDS_;

#pragma unroll
        for (int kk = 0; kk < BK; kk += 16) {
            uint32_t af[MI][4];
#pragma unroll
            for (int mi = 0; mi < MI; mi++) {
                uint32_t addr = (uint32_t)__cvta_generic_to_shared(
                    &Asb[(wm + mi * 16 + a_row) * LDS_ + kk + a_col]);
                asm volatile("ldmatrix.sync.aligned.m8n8.x4.shared.b16 {%0,%1,%2,%3}, [%4];"
                             : "=r"(af[mi][0]), "=r"(af[mi][1]), "=r"(af[mi][2]), "=r"(af[mi][3])
                             : "r"(addr));
            }
            uint32_t bf[NI][2];
#pragma unroll
            for (int ni = 0; ni < NI; ni++) {
                uint32_t addr = (uint32_t)__cvta_generic_to_shared(
                    &Bsb[(wn + ni * 8 + b_row) * LDS_ + kk + b_col]);
                asm volatile("ldmatrix.sync.aligned.m8n8.x2.shared.b16 {%0,%1}, [%2];"
                             : "=r"(bf[ni][0]), "=r"(bf[ni][1])
                             : "r"(addr));
            }
#pragma unroll
            for (int mi = 0; mi < MI; mi++) {
#pragma unroll
                for (int ni = 0; ni < NI; ni++) {
                    asm volatile(
                        "mma.sync.aligned.m16n8k16.row.col.f32.f16.f16.f32 "
                        "{%0,%1,%2,%3}, {%4,%5,%6,%7}, {%8,%9}, {%0,%1,%2,%3};"
                        : "+f"(acc[mi][ni][0]), "+f"(acc[mi][ni][1]),
                          "+f"(acc[mi][ni][2]), "+f"(acc[mi][ni][3])
                        : "r"(af[mi][0]), "r"(af[mi][1]), "r"(af[mi][2]), "r"(af[mi][3]),
                          "r"(bf[ni][0]), "r"(bf[ni][1]));
                }
            }
        }
    }

#pragma unroll
    for (int mi = 0; mi < MI; mi++) {
        int row0 = bm + wm + mi * 16 + lane / 4;
#pragma unroll
        for (int ni = 0; ni < NI; ni++) {
            int col = bn + wn + ni * 8 + 2 * (lane % 4);
            float2 bv = *(const float2*)&bias[col];
            float2 v0 = make_float2(acc[mi][ni][0] + bv.x, acc[mi][ni][1] + bv.y);
            float2 v1 = make_float2(acc[mi][ni][2] + bv.x, acc[mi][ni][3] + bv.y);
            *(float2*)&C[(size_t)row0 * N + col] = v0;
            *(float2*)&C[(size_t)(row0 + 8) * N + col] = v1;
        }
    }
}

// smem sizes (3 stages)
#define DSM_BIG   (3 * (128 + 128) * (64 + 8) * 2)   // 110592 (2 CTA/SM)
#define DSM_SMALL (3 * (64 + 64) * (64 + 8) * 2)     // 55296

#define GEMM_BIG   gemm_fp16_bias<128, 128, 64, 64, 32, 2>
#define GEMM_SMALL gemm_fp16_bias<64, 64, 64, 32, 32, 4>

// ---------------- setup / conversion kernels ----------------
__global__ void init_tokens_kernel(const int* __restrict__ target)
{
    int b = threadIdx.x;
    g_tokens[b * Tq + 0] = 0;  // SOS
    for (int t = 1; t < Tq; t++) g_tokens[b * Tq + t] = target[b * Tq + t - 1];
}

// float -> fp16, vectorized
__global__ void f2h_kernel(const float* __restrict__ src, __half* __restrict__ dst, int n4)
{
    int i = blockIdx.x * blockDim.x + threadIdx.x;
    if (i >= n4) return;
    float4 v = ((const float4*)src)[i];
    __half2 lo = __floats2half2_rn(v.x, v.y);
    __half2 hi = __floats2half2_rn(v.z, v.w);
    uint2 o;
    o.x = *(uint32_t*)&lo;
    o.y = *(uint32_t*)&hi;
    ((uint2*)dst)[i] = o;
}

// strided slice fp16: dst[n*K+k] = src[n*stride + off + k]
__global__ void slice_h_kernel(const float* __restrict__ src, __half* __restrict__ dst,
                               int N, int K, int stride, int off)
{
    int i = blockIdx.x * blockDim.x + threadIdx.x;
    if (i >= N * K) return;
    int n = i / K, k = i % K;
    dst[i] = __float2half_rn(src[(size_t)n * stride + off + k]);
}

// embedding rows for ALL steps; row r = t*Bq + b
__global__ void emb_h_kernel(const float* __restrict__ emb)
{
    int i = blockIdx.x * blockDim.x + threadIdx.x;
    int r = i / Hq, j = i % Hq;
    int t = r / Bq, b = r % Bq;
    g_e_h[i] = __float2half_rn(emb[(size_t)g_tokens[b * Tq + t] * Hq + j]);
}

__global__ void bias_cat_kernel(const float* __restrict__ bua, const float* __restrict__ bhh,
                                const float* __restrict__ ba)
{
    int i = blockIdx.x * blockDim.x + threadIdx.x;  // 4096
    g_bcat[i] = (i < Hq) ? bua[i] : bhh[i - Hq];
    g_bkA[i]  = (i < Hq) ? ba[i] : 0.f;
}

__global__ void copy_h0_kernel(float* __restrict__ dst, const float* __restrict__ src)
{
    int i = blockIdx.x * blockDim.x + threadIdx.x;
    float v = src[i];
    dst[i] = v;
    g_h_h[i] = __float2half_rn(v);
}

__global__ void copy_kernel(float* __restrict__ dst, const float* __restrict__ src)
{
    int i = blockIdx.x * blockDim.x + threadIdx.x;
    dst[i] = src[i];
}

// ---------------- fused attention + GRU ----------------
__global__ void __launch_bounds__(128)
attn_gru_kernel(const float* __restrict__ Va, const float* __restrict__ bva,
                float* __restrict__ att_out,
                const float* __restrict__ hcur, float* __restrict__ hnext, int t)
{
    const int b = blockIdx.x;
    const int tid = threadIdx.x;

    float partial[Sq];
#pragma unroll
    for (int s = 0; s < Sq; s++) partial[s] = 0.f;

    for (int h = tid; h < Hq; h += 128) {
        float qv = g_qgh[b * 4096 + h];
        float va = Va[h];
#pragma unroll
        for (int s = 0; s < Sq; s++) {
            float kw = g_keysA[((size_t)b * Sq + s) * 4096 + h];
            partial[s] += va * tanhf(kw + qv);
        }
    }

    __shared__ float red[4][Sq];
    __shared__ float w[Sq];
    __shared__ float gic_s[3 * Hq];
    int lane = tid & 31, warp = tid >> 5;
#pragma unroll
    for (int s = 0; s < Sq; s++) {
        float v = partial[s];
#pragma unroll
        for (int o = 16; o > 0; o >>= 1) v += __shfl_xor_sync(0xffffffffu, v, o);
        if (lane == 0) red[warp][s] = v;
    }
    __syncthreads();

    if (tid == 0) {
        float scv[Sq], mx = -1e30f;
#pragma unroll
        for (int s = 0; s < Sq; s++) {
            scv[s] = red[0][s] + red[1][s] + red[2][s] + red[3][s] + bva[0];
            mx = fmaxf(mx, scv[s]);
        }
        float sum = 0.f;
#pragma unroll
        for (int s = 0; s < Sq; s++) { scv[s] = expf(scv[s] - mx); sum += scv[s]; }
        float inv = 1.f / sum;
#pragma unroll
        for (int s = 0; s < Sq; s++) w[s] = scv[s] * inv;
    }
    __syncthreads();

    if (tid < Sq) att_out[(size_t)b * (Tq * Sq) + t * Sq + tid] = w[tid];

    // gic = sum_s w[s] * keysC[b,s,:]  (keysC = cols 1024.. of g_keysA)
    const float* kA = g_keysA + (size_t)b * Sq * 4096 + 1024;
    for (int j = tid; j < 3 * Hq; j += 128) {
        float acc = 0.f;
#pragma unroll
        for (int s = 0; s < Sq; s++)
            acc += w[s] * kA[(size_t)s * 4096 + j];
        gic_s[j] = acc;
    }
    __syncthreads();

    // GRU pointwise for row b
    const float* gie = g_gie + (size_t)(t * Bq + b) * 3 * Hq;
    const float* gh  = g_qgh + (size_t)b * 4096 + Hq;
    for (int j = tid; j < Hq; j += 128) {
        float r = 1.f / (1.f + expf(-(gie[j] + gic_s[j] + gh[j])));
        float z = 1.f / (1.f + expf(-(gie[Hq + j] + gic_s[Hq + j] + gh[Hq + j])));
        float n = tanhf(gie[2 * Hq + j] + gic_s[2 * Hq + j] + r * gh[2 * Hq + j]);
        float hv = (1.f - z) * n + z * hcur[b * Hq + j];
        hnext[b * Hq + j] = hv;
        __half hh = __float2half_rn(hv);
        g_hall[(size_t)(t * Bq + b) * Hq + j] = hh;
        g_h_h[b * Hq + j] = hh;
    }
}

// ---------------- batched log_softmax (row r = t*Bq + b -> out[b][t]) ----------------
__global__ void __launch_bounds__(256)
logsoftmax_all_kernel(float* __restrict__ out)
{
    const int r = blockIdx.x, tid = threadIdx.x;
    const int t = r / Bq, b = r % Bq;
    const float* row = g_logits_all + (size_t)r * Vq;

    float m = -1e30f, s = 0.f;
    for (int v = tid; v < Vq; v += 256) {
        float x = row[v];
        float nm = fmaxf(m, x);
        s = s * expf(m - nm) + expf(x - nm);
        m = nm;
    }
    int lane = tid & 31, warp = tid >> 5;
#pragma unroll
    for (int o = 16; o > 0; o >>= 1) {
        float m2 = __shfl_xor_sync(0xffffffffu, m, o);
        float s2 = __shfl_xor_sync(0xffffffffu, s, o);
        float nm = fmaxf(m, m2);
        s = s * expf(m - nm) + s2 * expf(m2 - nm);
        m = nm;
    }
    __shared__ float sm[8], ss[8];
    __shared__ float lse_sh;
    if (lane == 0) { sm[warp] = m; ss[warp] = s; }
    __syncthreads();
    if (tid == 0) {
        float M = sm[0], S = ss[0];
#pragma unroll
        for (int i = 1; i < 8; i++) {
            float nm = fmaxf(M, sm[i]);
            S = S * expf(M - nm) + ss[i] * expf(sm[i] - nm);
            M = nm;
        }
        lse_sh = M + logf(S);
    }
    __syncthreads();
    float lse = lse_sh;
    float* orow = out + ((size_t)b * Tq + t) * Vq;
    for (int v = tid; v < Vq; v += 256) orow[v] = row[v] - lse;
}

// ---------------- launch ----------------
extern "C" void kernel_launch(void* const* d_in, const int* in_sizes, int n_in,
                              void* d_out, int out_size)
{
    const float* enc_out = (const float*)d_in[0];
    const float* enc_hid = (const float*)d_in[1];
    const int*   target  = (const int*)  d_in[2];
    const float* emb     = (const float*)d_in[3];
    const float* Wa      = (const float*)d_in[4];
    const float* ba      = (const float*)d_in[5];
    const float* Ua      = (const float*)d_in[6];
    const float* bua     = (const float*)d_in[7];
    const float* Va      = (const float*)d_in[8];
    const float* bva     = (const float*)d_in[9];
    const float* W_ih    = (const float*)d_in[10];
    const float* W_hh    = (const float*)d_in[11];
    const float* b_ih    = (const float*)d_in[12];
    const float* b_hh    = (const float*)d_in[13];
    const float* W_out   = (const float*)d_in[14];
    const float* b_out   = (const float*)d_in[15];

    float* out = (float*)d_out;
    const size_t HID_OFF = (size_t)Bq * Tq * Vq;
    const size_t ATT_OFF = HID_OFF + (size_t)Bq * Hq;

    float *keysA, *gie, *h0, *h1, *logitsA, *bcat, *bkA, *qgh;
    __half *enc_h, *e_h, *WkA, *Wqh, *We, *h_h, *hall, *Wout_h;
    cudaGetSymbolAddress((void**)&keysA, g_keysA);
    cudaGetSymbolAddress((void**)&gie, g_gie);
    cudaGetSymbolAddress((void**)&h0, g_h0);
    cudaGetSymbolAddress((void**)&h1, g_h1);
    cudaGetSymbolAddress((void**)&logitsA, g_logits_all);
    cudaGetSymbolAddress((void**)&bcat, g_bcat);
    cudaGetSymbolAddress((void**)&bkA, g_bkA);
    cudaGetSymbolAddress((void**)&qgh, g_qgh);
    cudaGetSymbolAddress((void**)&enc_h, g_enc_h);
    cudaGetSymbolAddress((void**)&e_h, g_e_h);
    cudaGetSymbolAddress((void**)&WkA, g_WkA);
    cudaGetSymbolAddress((void**)&Wqh, g_Wqh);
    cudaGetSymbolAddress((void**)&We, g_We);
    cudaGetSymbolAddress((void**)&h_h, g_h_h);
    cudaGetSymbolAddress((void**)&hall, g_hall);
    cudaGetSymbolAddress((void**)&Wout_h, g_Wout_h);

    // raise dynamic smem limits (idempotent)
    cudaFuncSetAttribute((const void*)GEMM_BIG,
                         cudaFuncAttributeMaxDynamicSharedMemorySize, DSM_BIG);
    cudaFuncSetAttribute((const void*)GEMM_SMALL,
                         cudaFuncAttributeMaxDynamicSharedMemorySize, DSM_SMALL);

    // ---- setup (gie GEMM at launch #4 for ncu capture comparison) ----
    init_tokens_kernel<<<1, 256>>>(target);                                             // 1
    emb_h_kernel<<<(BT * Hq) / 256, 256>>>(emb);                                        // 2
    slice_h_kernel<<<(3 * Hq * Hq + 255) / 256, 256>>>(W_ih, We, 3 * Hq, Hq, 2 * Hq, 0);// 3
    // gi_e all steps = E @ W_e^T + b_ih  (M=2560, N=3072, K=1024)                      // 4
    GEMM_BIG<<<dim3(3 * Hq / 128, BT / 128), 256, DSM_BIG>>>(
        e_h, We, b_ih, gie, BT, 3 * Hq, Hq);

    f2h_kernel<<<(Bq * Sq * Hq / 4 + 255) / 256, 256>>>(enc_out, enc_h, Bq * Sq * Hq / 4);
    f2h_kernel<<<(Hq * Hq / 4 + 255) / 256, 256>>>(Wa, WkA, Hq * Hq / 4);
    slice_h_kernel<<<(3 * Hq * Hq + 255) / 256, 256>>>(W_ih, WkA + (size_t)Hq * Hq,
                                                       3 * Hq, Hq, 2 * Hq, Hq);
    bias_cat_kernel<<<16, 256>>>(bua, b_hh, ba);
    // keysA = enc @ [Wa;Wc]^T + [ba|0]  (M=2560, N=4096, K=1024)
    GEMM_BIG<<<dim3(4096 / 128, (Bq * Sq) / 128), 256, DSM_BIG>>>(
        enc_h, WkA, bkA, keysA, Bq * Sq, 4096, Hq);

    copy_h0_kernel<<<(Bq * Hq) / 256, 256>>>(h0, enc_hid);
    f2h_kernel<<<(Vq * Hq / 4 + 255) / 256, 256>>>(W_out, Wout_h, Vq * Hq / 4);
    f2h_kernel<<<(Hq * Hq / 4 + 255) / 256, 256>>>(Ua, Wqh, Hq * Hq / 4);
    f2h_kernel<<<(3 * Hq * Hq / 4 + 255) / 256, 256>>>(W_hh, Wqh + (size_t)Hq * Hq,
                                                       3 * Hq * Hq / 4);

    float* hcur = h0;
    float* hnext = h1;
    for (int t = 0; t < Tq; t++) {
        // [q | gh] = h @ [Ua; W_hh]^T + [bua | b_hh]  (M=256, N=4096, K=1024)
        GEMM_SMALL<<<dim3(4096 / 64, Bq / 64), 128, DSM_SMALL>>>(
            h_h, Wqh, bcat, qgh, Bq, 4096, Hq);
        attn_gru_kernel<<<Bq, 128>>>(Va, bva, out + ATT_OFF, hcur, hnext, t);
        float* tmp = hcur; hcur = hnext; hnext = tmp;
    }

    // logits for all steps = h_all @ W_out^T + b_out  (M=2560, N=32000, K=1024)
    GEMM_BIG<<<dim3(Vq / 128, BT / 128), 256, DSM_BIG>>>(
        hall, Wout_h, b_out, logitsA, BT, Vq, Hq);
    logsoftmax_all_kernel<<<BT, 256>>>(out);

    copy_kernel<<<(Bq * Hq) / 256, 256>>>(out + HID_OFF, hcur);
}